// round 13
// baseline (speedup 1.0000x reference)
#include <cuda_runtime.h>
#include <math.h>

#define NPTS   500000
#define MCLUS  50000
#define NTILE_ATT ((NPTS + 127) / 128)    // 3907
#define NTILE_M   ((MCLUS + 127) / 128)   // 391

__device__ float g_agg[(size_t)MCLUS * 132];   // 131 used + 1 pad
__device__ float g_h[(size_t)MCLUS * 128];

// ---------------- helpers ----------------
__device__ __forceinline__ void red4(float* addr, float a, float b, float c, float d) {
    asm volatile("red.global.add.v4.f32 [%0], {%1,%2,%3,%4};"
                 :: "l"(addr), "f"(a), "f"(b), "f"(c), "f"(d) : "memory");
}
__device__ __forceinline__ void cpasync16(void* smem_dst, const void* gsrc) {
    unsigned saddr = (unsigned)__cvta_generic_to_shared(smem_dst);
    asm volatile("cp.async.cg.shared.global [%0], [%1], 16;" :: "r"(saddr), "l"(gsrc));
}
__device__ __forceinline__ void cp_commit() { asm volatile("cp.async.commit_group;"); }
__device__ __forceinline__ void cp_wait0()  { asm volatile("cp.async.wait_group 0;" ::: "memory"); }

__device__ __forceinline__ unsigned cvt_tf32(float f) {
    unsigned x;
    asm("cvt.rna.tf32.f32 %0, %1;" : "=r"(x) : "f"(f));
    return x;
}
__device__ __forceinline__ void mma_tf32(float* c, unsigned a0, unsigned a1,
                                         unsigned a2, unsigned a3,
                                         unsigned b0, unsigned b1) {
    asm volatile(
        "mma.sync.aligned.m16n8k8.row.col.f32.tf32.tf32.f32 "
        "{%0,%1,%2,%3}, {%4,%5,%6,%7}, {%8,%9}, {%0,%1,%2,%3};"
        : "+f"(c[0]), "+f"(c[1]), "+f"(c[2]), "+f"(c[3])
        : "r"(a0), "r"(a1), "r"(a2), "r"(a3), "r"(b0), "r"(b1));
}

#define SA 136   // att A-tile row stride (floats): conflict-free
#define SB 72    // B-tile row stride (tf32 words): conflict-free

// ---------------- kernel 0: zero agg ----------------
__global__ void zero_agg_kernel() {
    const size_t total4 = (size_t)MCLUS * 132 / 4;
    float4* p = (float4*)g_agg;
    float4 z = make_float4(0.f, 0.f, 0.f, 0.f);
    for (size_t i = blockIdx.x * blockDim.x + threadIdx.x; i < total4;
         i += (size_t)gridDim.x * blockDim.x)
        p[i] = z;
}

// ============ kernel 1: attention MLP (tf32 MMA) + scatter ============
// Persistent, per-warp independent pipelines: warp w owns tile rows w*16..w*16+15.
__global__ void __launch_bounds__(256, 2) att_scatter_kernel(
    const float* __restrict__ feat, const float* __restrict__ pts,
    const float* __restrict__ ctr, const int* __restrict__ lab,
    const float* __restrict__ aW1, const float* __restrict__ ab1,
    const float* __restrict__ aW2, const float* __restrict__ ab2)
{
    extern __shared__ char dynRaw[];
    float*    sA  = (float*)dynRaw;                       // 128*SA floats
    unsigned* sWb = (unsigned*)(dynRaw + 128 * SA * 4);   // 136*SB tf32 bits
    float*    sB1 = (float*)(dynRaw + 128 * SA * 4 + 136 * SB * 4);  // 64
    float*    sA2 = sB1 + 64;          // 64
    float*    sAtt = sA2 + 64;         // 128
    int*      sLab = (int*)(sAtt + 128);  // 128
    float*    sb2p = (float*)(sLab + 128);

    const int tid = threadIdx.x;
    const float4* f4 = (const float4*)feat;

    for (int idx = tid; idx < 136 * 64; idx += 256) {
        int k = idx >> 6, n = idx & 63;
        float v = (k < 131) ? aW1[k * 64 + n] : 0.f;
        sWb[k * SB + n] = cvt_tf32(v);
    }
    if (tid < 64) { sB1[tid] = ab1[tid]; sA2[tid] = aW2[tid]; }
    if (tid == 0) *sb2p = ab2[0];
    __syncthreads();

    const int w = tid >> 5;
    const int lane = tid & 31;
    const int g = lane >> 2;
    const int t = lane & 3;
    const int rbase = w * 16;
    const float b2v = *sb2p;

    for (int tile = blockIdx.x; tile < NTILE_ATT; tile += gridDim.x) {
        const int gbase = tile * 128;

        for (int idx = lane; idx < 16 * 32; idx += 32) {
            int r = idx >> 5, c4 = idx & 31;
            int gr = gbase + rbase + r; if (gr >= NPTS) gr = NPTS - 1;
            cpasync16(sA + (rbase + r) * SA + c4 * 4, f4 + (size_t)gr * 32 + c4);
        }
        cp_commit();
        if (lane < 16) {
            int rl = rbase + lane;
            int row = gbase + rl;
            int rc = (row < NPTS) ? row : (NPTS - 1);
            int l = lab[rc];
            sLab[rl] = l;
            float* Ar = sA + rl * SA;
            Ar[128] = ctr[l * 3 + 0] - pts[rc * 3 + 0];
            Ar[129] = ctr[l * 3 + 1] - pts[rc * 3 + 1];
            Ar[130] = ctr[l * 3 + 2] - pts[rc * 3 + 2];
            Ar[131] = 0.f; Ar[132] = 0.f; Ar[133] = 0.f; Ar[134] = 0.f; Ar[135] = 0.f;
        }
        cp_wait0();
        __syncwarp();

        float acc[8][4];
#pragma unroll
        for (int nf = 0; nf < 8; nf++) {
            acc[nf][0] = 0.f; acc[nf][1] = 0.f; acc[nf][2] = 0.f; acc[nf][3] = 0.f;
        }

        const float* Ar0 = sA + (rbase + g) * SA;
        const float* Ar1 = Ar0 + 8 * SA;

#pragma unroll 1
        for (int kf = 0; kf < 17; kf++) {
            int k0 = kf * 8;
            unsigned a0 = cvt_tf32(Ar0[k0 + t]);
            unsigned a1 = cvt_tf32(Ar1[k0 + t]);
            unsigned a2 = cvt_tf32(Ar0[k0 + t + 4]);
            unsigned a3 = cvt_tf32(Ar1[k0 + t + 4]);
            const unsigned* B0 = sWb + (k0 + t) * SB + g;
            const unsigned* B1 = sWb + (k0 + t + 4) * SB + g;
#pragma unroll
            for (int nf = 0; nf < 8; nf++) {
                mma_tf32(acc[nf], a0, a1, a2, a3, B0[nf * 8], B1[nf * 8]);
            }
        }

        {
            float s0 = 0.f, s1 = 0.f;
#pragma unroll
            for (int nf = 0; nf < 8; nf++) {
                int c0 = nf * 8 + 2 * t, c1 = c0 + 1;
                float bb0 = sB1[c0], bb1 = sB1[c1];
                float w0 = sA2[c0], w1 = sA2[c1];
                s0 += fmaxf(acc[nf][0] + bb0, 0.f) * w0 + fmaxf(acc[nf][1] + bb1, 0.f) * w1;
                s1 += fmaxf(acc[nf][2] + bb0, 0.f) * w0 + fmaxf(acc[nf][3] + bb1, 0.f) * w1;
            }
            s0 += __shfl_xor_sync(0xffffffffu, s0, 1);
            s0 += __shfl_xor_sync(0xffffffffu, s0, 2);
            s1 += __shfl_xor_sync(0xffffffffu, s1, 1);
            s1 += __shfl_xor_sync(0xffffffffu, s1, 2);
            if (t == 0) {
                sAtt[rbase + g]     = 1.f / (1.f + expf(-(s0 + b2v)));
                sAtt[rbase + g + 8] = 1.f / (1.f + expf(-(s1 + b2v)));
            }
        }
        __syncwarp();

        for (int idx = lane; idx < 16 * 33; idx += 32) {
            int r = idx / 33, c = idx - r * 33;
            int rl = rbase + r;
            int grow = gbase + rl;
            if (grow < NPTS) {
                float a = sAtt[rl];
                int l = sLab[rl];
                float4 v = *(const float4*)(sA + rl * SA + c * 4);
                red4(g_agg + (size_t)l * 132 + c * 4,
                     v.x * a, v.y * a, v.z * a, v.w * a);
            }
        }
        __syncwarp();
    }
}

// ============ kernel 2: h = relu(agg @ oW1 + ob1)  (tf32 MMA, direct LDG A) ============
// grid (222, 2): y = 64-col slice; weights-only smem; 3 CTAs/SM
__global__ void __launch_bounds__(256, 3) gemmB_kernel(
    const float* __restrict__ oW1, const float* __restrict__ ob1)
{
    extern __shared__ char dynRaw[];
    unsigned* sWb = (unsigned*)dynRaw;   // 136*SB

    const int tid = threadIdx.x;
    const int slice = blockIdx.y;

    for (int idx = tid; idx < 136 * 64; idx += 256) {
        int k = idx >> 6, n = idx & 63;
        float v = (k < 131) ? oW1[k * 128 + slice * 64 + n] : 0.f;
        sWb[k * SB + n] = cvt_tf32(v);
    }
    __syncthreads();

    const int w = tid >> 5;
    const int lane = tid & 31;
    const int g = lane >> 2;
    const int t = lane & 3;
    const int rbase = w * 16;

    for (int tile = blockIdx.x; tile < NTILE_M; tile += gridDim.x) {
        const int gbase = tile * 128;
        int r0g = gbase + rbase + g;
        int r1g = r0g + 8;
        int r0c = (r0g < MCLUS) ? r0g : (MCLUS - 1);
        int r1c = (r1g < MCLUS) ? r1g : (MCLUS - 1);
        const float* Arow0 = g_agg + (size_t)r0c * 132;
        const float* Arow1 = g_agg + (size_t)r1c * 132;

        float acc[8][4];
#pragma unroll
        for (int nf = 0; nf < 8; nf++) {
            acc[nf][0] = 0.f; acc[nf][1] = 0.f; acc[nf][2] = 0.f; acc[nf][3] = 0.f;
        }

        // prefetch kf=0 fragments
        float p0 = __ldg(Arow0 + t);
        float p1 = __ldg(Arow1 + t);
        float p2 = __ldg(Arow0 + t + 4);
        float p3 = __ldg(Arow1 + t + 4);

#pragma unroll 1
        for (int kf = 0; kf < 17; kf++) {
            unsigned a0 = cvt_tf32(p0), a1 = cvt_tf32(p1);
            unsigned a2 = cvt_tf32(p2), a3 = cvt_tf32(p3);
            if (kf < 16) {
                int k0 = (kf + 1) * 8;
                p0 = __ldg(Arow0 + k0 + t);       // k <= 128+3 = 131, in-row
                p1 = __ldg(Arow1 + k0 + t);
                if (kf < 15) {
                    p2 = __ldg(Arow0 + k0 + t + 4);
                    p3 = __ldg(Arow1 + k0 + t + 4);
                } else {
                    p2 = 0.f; p3 = 0.f;           // k 132..135 = pad (B rows zero)
                }
            }
            int k0 = kf * 8;
            const unsigned* B0 = sWb + (k0 + t) * SB + g;
            const unsigned* B1 = sWb + (k0 + t + 4) * SB + g;
#pragma unroll
            for (int nf = 0; nf < 8; nf++) {
                mma_tf32(acc[nf], a0, a1, a2, a3, B0[nf * 8], B1[nf * 8]);
            }
        }

#pragma unroll
        for (int nf = 0; nf < 8; nf++) {
            int c0 = slice * 64 + nf * 8 + 2 * t;
            float bb0 = __ldg(ob1 + c0), bb1 = __ldg(ob1 + c0 + 1);
            if (r0g < MCLUS)
                *(float2*)(g_h + (size_t)r0g * 128 + c0) =
                    make_float2(fmaxf(acc[nf][0] + bb0, 0.f),
                                fmaxf(acc[nf][1] + bb1, 0.f));
            if (r1g < MCLUS)
                *(float2*)(g_h + (size_t)r1g * 128 + c0) =
                    make_float2(fmaxf(acc[nf][2] + bb0, 0.f),
                                fmaxf(acc[nf][3] + bb1, 0.f));
        }
    }
}

// ============ kernel 3: out = relu(h @ oW2 + ob2)  (tf32 MMA, direct LDG A) ============
// grid (111, 4): y = 64-col slice; weights-only smem; 3 CTAs/SM
__global__ void __launch_bounds__(256, 3) gemmC_kernel(
    const float* __restrict__ oW2, const float* __restrict__ ob2,
    float* __restrict__ out)
{
    extern __shared__ char dynRaw[];
    unsigned* sWb = (unsigned*)dynRaw;   // 128*SB

    const int tid = threadIdx.x;
    const int slice = blockIdx.y;

    for (int idx = tid; idx < 128 * 64; idx += 256) {
        int k = idx >> 6, n = idx & 63;
        sWb[k * SB + n] = cvt_tf32(oW2[k * 256 + slice * 64 + n]);
    }
    __syncthreads();

    const int w = tid >> 5;
    const int lane = tid & 31;
    const int g = lane >> 2;
    const int t = lane & 3;
    const int rbase = w * 16;

    for (int tile = blockIdx.x; tile < NTILE_M; tile += gridDim.x) {
        const int gbase = tile * 128;
        int r0g = gbase + rbase + g;
        int r1g = r0g + 8;
        int r0c = (r0g < MCLUS) ? r0g : (MCLUS - 1);
        int r1c = (r1g < MCLUS) ? r1g : (MCLUS - 1);
        const float* Arow0 = g_h + (size_t)r0c * 128;
        const float* Arow1 = g_h + (size_t)r1c * 128;

        float acc[8][4];
#pragma unroll
        for (int nf = 0; nf < 8; nf++) {
            acc[nf][0] = 0.f; acc[nf][1] = 0.f; acc[nf][2] = 0.f; acc[nf][3] = 0.f;
        }

        float p0 = __ldg(Arow0 + t);
        float p1 = __ldg(Arow1 + t);
        float p2 = __ldg(Arow0 + t + 4);
        float p3 = __ldg(Arow1 + t + 4);

#pragma unroll 1
        for (int kf = 0; kf < 16; kf++) {
            unsigned a0 = cvt_tf32(p0), a1 = cvt_tf32(p1);
            unsigned a2 = cvt_tf32(p2), a3 = cvt_tf32(p3);
            if (kf < 15) {
                int k0 = (kf + 1) * 8;
                p0 = __ldg(Arow0 + k0 + t);
                p1 = __ldg(Arow1 + k0 + t);
                p2 = __ldg(Arow0 + k0 + t + 4);
                p3 = __ldg(Arow1 + k0 + t + 4);
            }
            int k0 = kf * 8;
            const unsigned* B0 = sWb + (k0 + t) * SB + g;
            const unsigned* B1 = sWb + (k0 + t + 4) * SB + g;
#pragma unroll
            for (int nf = 0; nf < 8; nf++) {
                mma_tf32(acc[nf], a0, a1, a2, a3, B0[nf * 8], B1[nf * 8]);
            }
        }

#pragma unroll
        for (int nf = 0; nf < 8; nf++) {
            int c0 = slice * 64 + nf * 8 + 2 * t;
            float bb0 = __ldg(ob2 + c0), bb1 = __ldg(ob2 + c0 + 1);
            if (r0g < MCLUS)
                *(float2*)(out + (size_t)r0g * 256 + c0) =
                    make_float2(fmaxf(acc[nf][0] + bb0, 0.f),
                                fmaxf(acc[nf][1] + bb1, 0.f));
            if (r1g < MCLUS)
                *(float2*)(out + (size_t)r1g * 256 + c0) =
                    make_float2(fmaxf(acc[nf][2] + bb0, 0.f),
                                fmaxf(acc[nf][3] + bb1, 0.f));
        }
    }
}

extern "C" void kernel_launch(void* const* d_in, const int* in_sizes, int n_in,
                              void* d_out, int out_size) {
    const float* feat = (const float*)d_in[0];
    const float* pts  = (const float*)d_in[1];
    const float* ctr  = (const float*)d_in[2];
    const int*   lab  = (const int*)d_in[3];
    const float* aW1  = (const float*)d_in[4];
    const float* ab1  = (const float*)d_in[5];
    const float* aW2  = (const float*)d_in[6];
    const float* ab2  = (const float*)d_in[7];
    const float* oW1  = (const float*)d_in[8];
    const float* ob1  = (const float*)d_in[9];
    const float* oW2  = (const float*)d_in[10];
    const float* ob2  = (const float*)d_in[11];
    float* out = (float*)d_out;

    const int attSmem = 128 * SA * 4 + 136 * SB * 4 + (64 + 64 + 128) * 4 + 128 * 4 + 16;
    const int bSmem   = 136 * SB * 4;
    const int cSmem   = 128 * SB * 4;

    static int inited = 0;
    if (!inited) {
        cudaFuncSetAttribute(att_scatter_kernel, cudaFuncAttributeMaxDynamicSharedMemorySize, attSmem);
        cudaFuncSetAttribute(gemmB_kernel, cudaFuncAttributeMaxDynamicSharedMemorySize, bSmem);
        cudaFuncSetAttribute(gemmC_kernel, cudaFuncAttributeMaxDynamicSharedMemorySize, cSmem);
        inited = 1;
    }

    zero_agg_kernel<<<2048, 256>>>();
    att_scatter_kernel<<<296, 256, attSmem>>>(feat, pts, ctr, lab,
                                              aW1, ab1, aW2, ab2);
    gemmB_kernel<<<dim3(222, 2), 256, bSmem>>>(oW1, ob1);
    gemmC_kernel<<<dim3(111, 4), 256, cSmem>>>(oW2, ob2, out);
}

// round 14
// speedup vs baseline: 1.0649x; 1.0649x over previous
#include <cuda_runtime.h>
#include <math.h>

#define NPTS   500000
#define MCLUS  50000
#define NTILE_ATT ((NPTS + 127) / 128)    // 3907
#define NTILE_M   ((MCLUS + 127) / 128)   // 391

__device__ float g_agg[(size_t)MCLUS * 132];   // 131 used + 1 pad
__device__ float g_h[(size_t)MCLUS * 128];

// ---------------- helpers ----------------
__device__ __forceinline__ void red4(float* addr, float a, float b, float c, float d) {
    asm volatile("red.global.add.v4.f32 [%0], {%1,%2,%3,%4};"
                 :: "l"(addr), "f"(a), "f"(b), "f"(c), "f"(d) : "memory");
}
__device__ __forceinline__ void cpasync16(void* smem_dst, const void* gsrc) {
    unsigned saddr = (unsigned)__cvta_generic_to_shared(smem_dst);
    asm volatile("cp.async.cg.shared.global [%0], [%1], 16;" :: "r"(saddr), "l"(gsrc));
}
__device__ __forceinline__ void cp_commit() { asm volatile("cp.async.commit_group;"); }
__device__ __forceinline__ void cp_wait0()  { asm volatile("cp.async.wait_group 0;" ::: "memory"); }

__device__ __forceinline__ unsigned cvt_tf32(float f) {
    unsigned x;
    asm("cvt.rna.tf32.f32 %0, %1;" : "=r"(x) : "f"(f));
    return x;
}
__device__ __forceinline__ void mma_tf32(float* c, unsigned a0, unsigned a1,
                                         unsigned a2, unsigned a3,
                                         unsigned b0, unsigned b1) {
    asm volatile(
        "mma.sync.aligned.m16n8k8.row.col.f32.tf32.tf32.f32 "
        "{%0,%1,%2,%3}, {%4,%5,%6,%7}, {%8,%9}, {%0,%1,%2,%3};"
        : "+f"(c[0]), "+f"(c[1]), "+f"(c[2]), "+f"(c[3])
        : "r"(a0), "r"(a1), "r"(a2), "r"(a3), "r"(b0), "r"(b1));
}

#define SA  136   // A-tile row stride (floats): conflict-free
#define SWR 40    // B half row stride (words): LDS.128 phase-conflict-free

// per-warp kf body: 8 MMAs, 4 B-LDS.128, 4 A-LDS.32.
// acc[q] covers cols q*8 + {2t,2t+1}  (q<4 from sW0 half, q>=4 from sW1 half)
#define MMA_KF16(sW0_, sW1_)                                                  \
    {                                                                         \
        int kt  = kf * 8 + t;                                                 \
        int kt4 = kt + 4;                                                     \
        unsigned a0 = cvt_tf32(Ar0[kt]);                                      \
        unsigned a1 = cvt_tf32(Ar1[kt]);                                      \
        unsigned a2 = cvt_tf32(Ar0[kt4]);                                     \
        unsigned a3 = cvt_tf32(Ar1[kt4]);                                     \
        uint4 blo  = *(const uint4*)(sW0_ + kt  * SWR + g * 4);               \
        uint4 bhi  = *(const uint4*)(sW1_ + kt  * SWR + g * 4);               \
        uint4 blo4 = *(const uint4*)(sW0_ + kt4 * SWR + g * 4);               \
        uint4 bhi4 = *(const uint4*)(sW1_ + kt4 * SWR + g * 4);               \
        mma_tf32(acc[0], a0, a1, a2, a3, blo.x, blo4.x);                      \
        mma_tf32(acc[1], a0, a1, a2, a3, blo.y, blo4.y);                      \
        mma_tf32(acc[2], a0, a1, a2, a3, blo.z, blo4.z);                      \
        mma_tf32(acc[3], a0, a1, a2, a3, blo.w, blo4.w);                      \
        mma_tf32(acc[4], a0, a1, a2, a3, bhi.x, bhi4.x);                      \
        mma_tf32(acc[5], a0, a1, a2, a3, bhi.y, bhi4.y);                      \
        mma_tf32(acc[6], a0, a1, a2, a3, bhi.z, bhi4.z);                      \
        mma_tf32(acc[7], a0, a1, a2, a3, bhi.w, bhi4.w);                      \
    }

// store weight value (k, n) into split layout
#define STORE_WB(sW0_, sW1_, k_, n_, val_)                                    \
    {                                                                         \
        int nf_ = (n_) >> 3, gg_ = (n_) & 7;                                  \
        unsigned* dst_ = (nf_ < 4) ? (sW0_) : (sW1_);                         \
        dst_[(k_) * SWR + gg_ * 4 + (nf_ & 3)] = cvt_tf32(val_);              \
    }

// ---------------- kernel 0: zero agg ----------------
__global__ void zero_agg_kernel() {
    const size_t total4 = (size_t)MCLUS * 132 / 4;
    float4* p = (float4*)g_agg;
    float4 z = make_float4(0.f, 0.f, 0.f, 0.f);
    for (size_t i = blockIdx.x * blockDim.x + threadIdx.x; i < total4;
         i += (size_t)gridDim.x * blockDim.x)
        p[i] = z;
}

// ============ kernel 1: attention MLP (tf32 MMA) + scatter ============
// Persistent, per-warp independent pipelines: warp w owns tile rows w*16..w*16+15.
__global__ void __launch_bounds__(256, 2) att_scatter_kernel(
    const float* __restrict__ feat, const float* __restrict__ pts,
    const float* __restrict__ ctr, const int* __restrict__ lab,
    const float* __restrict__ aW1, const float* __restrict__ ab1,
    const float* __restrict__ aW2, const float* __restrict__ ab2)
{
    extern __shared__ char dynRaw[];
    float*    sA  = (float*)dynRaw;                       // 128*SA floats
    unsigned* sW0 = (unsigned*)(dynRaw + 128 * SA * 4);   // 136*SWR
    unsigned* sW1 = sW0 + 136 * SWR;                      // 136*SWR
    float*    sB1 = (float*)(sW1 + 136 * SWR);            // 64
    float*    sA2 = sB1 + 64;          // 64
    float*    sAtt = sA2 + 64;         // 128
    int*      sLab = (int*)(sAtt + 128);  // 128
    float*    sb2p = (float*)(sLab + 128);

    const int tid = threadIdx.x;
    const float4* f4 = (const float4*)feat;

    for (int idx = tid; idx < 136 * 64; idx += 256) {
        int k = idx >> 6, n = idx & 63;
        float v = (k < 131) ? aW1[k * 64 + n] : 0.f;
        STORE_WB(sW0, sW1, k, n, v)
    }
    if (tid < 64) { sB1[tid] = ab1[tid]; sA2[tid] = aW2[tid]; }
    if (tid == 0) *sb2p = ab2[0];
    __syncthreads();

    const int w = tid >> 5;
    const int lane = tid & 31;
    const int g = lane >> 2;
    const int t = lane & 3;
    const int rbase = w * 16;
    const float b2v = *sb2p;

    for (int tile = blockIdx.x; tile < NTILE_ATT; tile += gridDim.x) {
        const int gbase = tile * 128;

        for (int idx = lane; idx < 16 * 32; idx += 32) {
            int r = idx >> 5, c4 = idx & 31;
            int gr = gbase + rbase + r; if (gr >= NPTS) gr = NPTS - 1;
            cpasync16(sA + (rbase + r) * SA + c4 * 4, f4 + (size_t)gr * 32 + c4);
        }
        cp_commit();
        if (lane < 16) {
            int rl = rbase + lane;
            int row = gbase + rl;
            int rc = (row < NPTS) ? row : (NPTS - 1);
            int l = lab[rc];
            sLab[rl] = l;
            float* Ar = sA + rl * SA;
            Ar[128] = ctr[l * 3 + 0] - pts[rc * 3 + 0];
            Ar[129] = ctr[l * 3 + 1] - pts[rc * 3 + 1];
            Ar[130] = ctr[l * 3 + 2] - pts[rc * 3 + 2];
            Ar[131] = 0.f; Ar[132] = 0.f; Ar[133] = 0.f; Ar[134] = 0.f; Ar[135] = 0.f;
        }
        cp_wait0();
        __syncwarp();

        float acc[8][4];
#pragma unroll
        for (int nf = 0; nf < 8; nf++) {
            acc[nf][0] = 0.f; acc[nf][1] = 0.f; acc[nf][2] = 0.f; acc[nf][3] = 0.f;
        }

        const float* Ar0 = sA + (rbase + g) * SA;
        const float* Ar1 = Ar0 + 8 * SA;

#pragma unroll 1
        for (int kf = 0; kf < 17; kf++) {
            MMA_KF16(sW0, sW1)
        }

        {
            float s0 = 0.f, s1 = 0.f;
#pragma unroll
            for (int nf = 0; nf < 8; nf++) {
                int c0 = nf * 8 + 2 * t, c1 = c0 + 1;
                float bb0 = sB1[c0], bb1 = sB1[c1];
                float w0 = sA2[c0], w1 = sA2[c1];
                s0 += fmaxf(acc[nf][0] + bb0, 0.f) * w0 + fmaxf(acc[nf][1] + bb1, 0.f) * w1;
                s1 += fmaxf(acc[nf][2] + bb0, 0.f) * w0 + fmaxf(acc[nf][3] + bb1, 0.f) * w1;
            }
            s0 += __shfl_xor_sync(0xffffffffu, s0, 1);
            s0 += __shfl_xor_sync(0xffffffffu, s0, 2);
            s1 += __shfl_xor_sync(0xffffffffu, s1, 1);
            s1 += __shfl_xor_sync(0xffffffffu, s1, 2);
            if (t == 0) {
                sAtt[rbase + g]     = 1.f / (1.f + expf(-(s0 + b2v)));
                sAtt[rbase + g + 8] = 1.f / (1.f + expf(-(s1 + b2v)));
            }
        }
        __syncwarp();

        for (int idx = lane; idx < 16 * 33; idx += 32) {
            int r = idx / 33, c = idx - r * 33;
            int rl = rbase + r;
            int grow = gbase + rl;
            if (grow < NPTS) {
                float a = sAtt[rl];
                int l = sLab[rl];
                float4 v = *(const float4*)(sA + rl * SA + c * 4);
                red4(g_agg + (size_t)l * 132 + c * 4,
                     v.x * a, v.y * a, v.z * a, v.w * a);
            }
        }
        __syncwarp();
    }
}

// ============ kernel 2: h = relu(agg @ oW1 + ob1)  (tf32 MMA) ============
// grid (148, 2): y = 64-col slice; persistent, per-warp pipelines
__global__ void __launch_bounds__(256, 2) gemmB_kernel(
    const float* __restrict__ oW1, const float* __restrict__ ob1)
{
    extern __shared__ char dynRaw[];
    float*    sA  = (float*)dynRaw;                       // 128*SA
    unsigned* sW0 = (unsigned*)(dynRaw + 128 * SA * 4);   // 136*SWR
    unsigned* sW1 = sW0 + 136 * SWR;

    const int tid = threadIdx.x;
    const int slice = blockIdx.y;
    const float4* a4 = (const float4*)g_agg;   // 33 f4/row

    for (int idx = tid; idx < 136 * 64; idx += 256) {
        int k = idx >> 6, n = idx & 63;
        float v = (k < 131) ? oW1[k * 128 + slice * 64 + n] : 0.f;
        STORE_WB(sW0, sW1, k, n, v)
    }
    __syncthreads();

    const int w = tid >> 5;
    const int lane = tid & 31;
    const int g = lane >> 2;
    const int t = lane & 3;
    const int rbase = w * 16;

    float bias0[8], bias1[8];
#pragma unroll
    for (int nf = 0; nf < 8; nf++) {
        int c0 = slice * 64 + nf * 8 + 2 * t;
        bias0[nf] = __ldg(ob1 + c0);
        bias1[nf] = __ldg(ob1 + c0 + 1);
    }

    for (int tile = blockIdx.x; tile < NTILE_M; tile += gridDim.x) {
        const int gbase = tile * 128;

        for (int idx = lane; idx < 16 * 33; idx += 32) {
            int r = idx / 33, c4 = idx - r * 33;
            int gr = gbase + rbase + r; if (gr >= MCLUS) gr = MCLUS - 1;
            cpasync16(sA + (rbase + r) * SA + c4 * 4, a4 + (size_t)gr * 33 + c4);
        }
        cp_commit();
        if (lane < 16) {   // zero A cols 132..135
            float* Ar = sA + (rbase + lane) * SA;
            Ar[132] = 0.f; Ar[133] = 0.f; Ar[134] = 0.f; Ar[135] = 0.f;
        }
        cp_wait0();
        __syncwarp();

        float acc[8][4];
#pragma unroll
        for (int nf = 0; nf < 8; nf++) {
            acc[nf][0] = 0.f; acc[nf][1] = 0.f; acc[nf][2] = 0.f; acc[nf][3] = 0.f;
        }

        const float* Ar0 = sA + (rbase + g) * SA;
        const float* Ar1 = Ar0 + 8 * SA;

#pragma unroll 1
        for (int kf = 0; kf < 17; kf++) {
            MMA_KF16(sW0, sW1)
        }

        int r0 = gbase + rbase + g;
        int r1 = r0 + 8;
#pragma unroll
        for (int nf = 0; nf < 8; nf++) {
            int c0 = slice * 64 + nf * 8 + 2 * t;
            if (r0 < MCLUS)
                *(float2*)(g_h + (size_t)r0 * 128 + c0) =
                    make_float2(fmaxf(acc[nf][0] + bias0[nf], 0.f),
                                fmaxf(acc[nf][1] + bias1[nf], 0.f));
            if (r1 < MCLUS)
                *(float2*)(g_h + (size_t)r1 * 128 + c0) =
                    make_float2(fmaxf(acc[nf][2] + bias0[nf], 0.f),
                                fmaxf(acc[nf][3] + bias1[nf], 0.f));
        }
        __syncwarp();
    }
}

// ============ kernel 3: out = relu(h @ oW2 + ob2)  (tf32 MMA) ============
// grid (74, 4): y = 64-col slice; persistent, per-warp pipelines
__global__ void __launch_bounds__(256, 2) gemmC_kernel(
    const float* __restrict__ oW2, const float* __restrict__ ob2,
    float* __restrict__ out)
{
    extern __shared__ char dynRaw[];
    float*    sA  = (float*)dynRaw;                       // 128*SA
    unsigned* sW0 = (unsigned*)(dynRaw + 128 * SA * 4);   // 128*SWR
    unsigned* sW1 = sW0 + 128 * SWR;

    const int tid = threadIdx.x;
    const int slice = blockIdx.y;
    const float4* h4 = (const float4*)g_h;   // 32 f4/row

    for (int idx = tid; idx < 128 * 64; idx += 256) {
        int k = idx >> 6, n = idx & 63;
        STORE_WB(sW0, sW1, k, n, oW2[k * 256 + slice * 64 + n])
    }
    __syncthreads();

    const int w = tid >> 5;
    const int lane = tid & 31;
    const int g = lane >> 2;
    const int t = lane & 3;
    const int rbase = w * 16;

    float bias0[8], bias1[8];
#pragma unroll
    for (int nf = 0; nf < 8; nf++) {
        int c0 = slice * 64 + nf * 8 + 2 * t;
        bias0[nf] = __ldg(ob2 + c0);
        bias1[nf] = __ldg(ob2 + c0 + 1);
    }

    for (int tile = blockIdx.x; tile < NTILE_M; tile += gridDim.x) {
        const int gbase = tile * 128;

        for (int idx = lane; idx < 16 * 32; idx += 32) {
            int r = idx >> 5, c4 = idx & 31;
            int gr = gbase + rbase + r; if (gr >= MCLUS) gr = MCLUS - 1;
            cpasync16(sA + (rbase + r) * SA + c4 * 4, h4 + (size_t)gr * 32 + c4);
        }
        cp_commit();
        cp_wait0();
        __syncwarp();

        float acc[8][4];
#pragma unroll
        for (int nf = 0; nf < 8; nf++) {
            acc[nf][0] = 0.f; acc[nf][1] = 0.f; acc[nf][2] = 0.f; acc[nf][3] = 0.f;
        }

        const float* Ar0 = sA + (rbase + g) * SA;
        const float* Ar1 = Ar0 + 8 * SA;

#pragma unroll 1
        for (int kf = 0; kf < 16; kf++) {
            MMA_KF16(sW0, sW1)
        }

        int r0 = gbase + rbase + g;
        int r1 = r0 + 8;
#pragma unroll
        for (int nf = 0; nf < 8; nf++) {
            int c0 = slice * 64 + nf * 8 + 2 * t;
            if (r0 < MCLUS)
                *(float2*)(out + (size_t)r0 * 256 + c0) =
                    make_float2(fmaxf(acc[nf][0] + bias0[nf], 0.f),
                                fmaxf(acc[nf][1] + bias1[nf], 0.f));
            if (r1 < MCLUS)
                *(float2*)(out + (size_t)r1 * 256 + c0) =
                    make_float2(fmaxf(acc[nf][2] + bias0[nf], 0.f),
                                fmaxf(acc[nf][3] + bias1[nf], 0.f));
        }
        __syncwarp();
    }
}

extern "C" void kernel_launch(void* const* d_in, const int* in_sizes, int n_in,
                              void* d_out, int out_size) {
    const float* feat = (const float*)d_in[0];
    const float* pts  = (const float*)d_in[1];
    const float* ctr  = (const float*)d_in[2];
    const int*   lab  = (const int*)d_in[3];
    const float* aW1  = (const float*)d_in[4];
    const float* ab1  = (const float*)d_in[5];
    const float* aW2  = (const float*)d_in[6];
    const float* ab2  = (const float*)d_in[7];
    const float* oW1  = (const float*)d_in[8];
    const float* ob1  = (const float*)d_in[9];
    const float* oW2  = (const float*)d_in[10];
    const float* ob2  = (const float*)d_in[11];
    float* out = (float*)d_out;

    const int attSmem = 128 * SA * 4 + 2 * 136 * SWR * 4 + (64 + 64 + 128) * 4 + 128 * 4 + 16;
    const int bSmem   = 128 * SA * 4 + 2 * 136 * SWR * 4;
    const int cSmem   = 128 * SA * 4 + 2 * 128 * SWR * 4;

    static int inited = 0;
    if (!inited) {
        cudaFuncSetAttribute(att_scatter_kernel, cudaFuncAttributeMaxDynamicSharedMemorySize, attSmem);
        cudaFuncSetAttribute(gemmB_kernel, cudaFuncAttributeMaxDynamicSharedMemorySize, bSmem);
        cudaFuncSetAttribute(gemmC_kernel, cudaFuncAttributeMaxDynamicSharedMemorySize, cSmem);
        inited = 1;
    }

    zero_agg_kernel<<<2048, 256>>>();
    att_scatter_kernel<<<296, 256, attSmem>>>(feat, pts, ctr, lab,
                                              aW1, ab1, aW2, ab2);
    gemmB_kernel<<<dim3(148, 2), 256, bSmem>>>(oW1, ob1);
    gemmC_kernel<<<dim3(74, 4), 256, cSmem>>>(oW2, ob2, out);
}

// round 15
// speedup vs baseline: 1.0822x; 1.0162x over previous
#include <cuda_runtime.h>
#include <math.h>

#define NPTS   500000
#define MCLUS  50000
#define NTILE_ATT ((NPTS + 127) / 128)    // 3907
#define NTILE_M   ((MCLUS + 127) / 128)   // 391

__device__ float g_agg[(size_t)MCLUS * 132];   // 131 used + 1 pad
__device__ float g_h[(size_t)MCLUS * 128];

// ---------------- helpers ----------------
__device__ __forceinline__ void red4(float* addr, float a, float b, float c, float d) {
    asm volatile("red.global.add.v4.f32 [%0], {%1,%2,%3,%4};"
                 :: "l"(addr), "f"(a), "f"(b), "f"(c), "f"(d) : "memory");
}
__device__ __forceinline__ void cpasync16(void* smem_dst, const void* gsrc) {
    unsigned saddr = (unsigned)__cvta_generic_to_shared(smem_dst);
    asm volatile("cp.async.cg.shared.global [%0], [%1], 16;" :: "r"(saddr), "l"(gsrc));
}
__device__ __forceinline__ void cp_commit() { asm volatile("cp.async.commit_group;"); }
__device__ __forceinline__ void cp_wait0()  { asm volatile("cp.async.wait_group 0;" ::: "memory"); }

__device__ __forceinline__ unsigned cvt_tf32(float f) {
    unsigned x;
    asm("cvt.rna.tf32.f32 %0, %1;" : "=r"(x) : "f"(f));
    return x;
}
__device__ __forceinline__ void mma_tf32(float* c, unsigned a0, unsigned a1,
                                         unsigned a2, unsigned a3,
                                         unsigned b0, unsigned b1) {
    asm volatile(
        "mma.sync.aligned.m16n8k8.row.col.f32.tf32.tf32.f32 "
        "{%0,%1,%2,%3}, {%4,%5,%6,%7}, {%8,%9}, {%0,%1,%2,%3};"
        : "+f"(c[0]), "+f"(c[1]), "+f"(c[2]), "+f"(c[3])
        : "r"(a0), "r"(a1), "r"(a2), "r"(a3), "r"(b0), "r"(b1));
}

#define SA 136   // A-tile row stride (floats): conflict-free
#define SB 72    // B-tile row stride (tf32 words): conflict-free

// ---------------- kernel 0: zero agg ----------------
__global__ void zero_agg_kernel() {
    const size_t total4 = (size_t)MCLUS * 132 / 4;
    float4* p = (float4*)g_agg;
    float4 z = make_float4(0.f, 0.f, 0.f, 0.f);
    for (size_t i = blockIdx.x * blockDim.x + threadIdx.x; i < total4;
         i += (size_t)gridDim.x * blockDim.x)
        p[i] = z;
}

// ============ kernel 1: attention MLP (tf32 MMA) + scatter ============
// Persistent, per-warp independent pipelines: warp w owns tile rows w*16..w*16+15.
__global__ void __launch_bounds__(256, 2) att_scatter_kernel(
    const float* __restrict__ feat, const float* __restrict__ pts,
    const float* __restrict__ ctr, const int* __restrict__ lab,
    const float* __restrict__ aW1, const float* __restrict__ ab1,
    const float* __restrict__ aW2, const float* __restrict__ ab2)
{
    extern __shared__ char dynRaw[];
    float*    sA  = (float*)dynRaw;                       // 128*SA floats
    unsigned* sWb = (unsigned*)(dynRaw + 128 * SA * 4);   // 136*SB tf32 bits
    float*    sB1 = (float*)(dynRaw + 128 * SA * 4 + 136 * SB * 4);  // 64
    float*    sA2 = sB1 + 64;          // 64
    float*    sAtt = sA2 + 64;         // 128
    int*      sLab = (int*)(sAtt + 128);  // 128
    float*    sb2p = (float*)(sLab + 128);

    const int tid = threadIdx.x;
    const float4* f4 = (const float4*)feat;

    for (int idx = tid; idx < 136 * 64; idx += 256) {
        int k = idx >> 6, n = idx & 63;
        float v = (k < 131) ? aW1[k * 64 + n] : 0.f;
        sWb[k * SB + n] = cvt_tf32(v);
    }
    if (tid < 64) { sB1[tid] = ab1[tid]; sA2[tid] = aW2[tid]; }
    if (tid == 0) *sb2p = ab2[0];
    __syncthreads();

    const int w = tid >> 5;
    const int lane = tid & 31;
    const int g = lane >> 2;
    const int t = lane & 3;
    const int rbase = w * 16;
    const float b2v = *sb2p;

    for (int tile = blockIdx.x; tile < NTILE_ATT; tile += gridDim.x) {
        const int gbase = tile * 128;

        for (int idx = lane; idx < 16 * 32; idx += 32) {
            int r = idx >> 5, c4 = idx & 31;
            int gr = gbase + rbase + r; if (gr >= NPTS) gr = NPTS - 1;
            cpasync16(sA + (rbase + r) * SA + c4 * 4, f4 + (size_t)gr * 32 + c4);
        }
        cp_commit();
        if (lane < 16) {
            int rl = rbase + lane;
            int row = gbase + rl;
            int rc = (row < NPTS) ? row : (NPTS - 1);
            int l = lab[rc];
            sLab[rl] = l;
            float* Ar = sA + rl * SA;
            Ar[128] = ctr[l * 3 + 0] - pts[rc * 3 + 0];
            Ar[129] = ctr[l * 3 + 1] - pts[rc * 3 + 1];
            Ar[130] = ctr[l * 3 + 2] - pts[rc * 3 + 2];
            Ar[131] = 0.f; Ar[132] = 0.f; Ar[133] = 0.f; Ar[134] = 0.f; Ar[135] = 0.f;
        }
        cp_wait0();
        __syncwarp();

        float acc[8][4];
#pragma unroll
        for (int nf = 0; nf < 8; nf++) {
            acc[nf][0] = 0.f; acc[nf][1] = 0.f; acc[nf][2] = 0.f; acc[nf][3] = 0.f;
        }

        const float* Ar0 = sA + (rbase + g) * SA;
        const float* Ar1 = Ar0 + 8 * SA;

#pragma unroll
        for (int kf = 0; kf < 17; kf++) {
            int k0 = kf * 8;
            unsigned a0 = cvt_tf32(Ar0[k0 + t]);
            unsigned a1 = cvt_tf32(Ar1[k0 + t]);
            unsigned a2 = cvt_tf32(Ar0[k0 + t + 4]);
            unsigned a3 = cvt_tf32(Ar1[k0 + t + 4]);
            const unsigned* B0 = sWb + (k0 + t) * SB + g;
            const unsigned* B1 = sWb + (k0 + t + 4) * SB + g;
#pragma unroll
            for (int nf = 0; nf < 8; nf++) {
                mma_tf32(acc[nf], a0, a1, a2, a3, B0[nf * 8], B1[nf * 8]);
            }
        }

        {
            float s0 = 0.f, s1 = 0.f;
#pragma unroll
            for (int nf = 0; nf < 8; nf++) {
                int c0 = nf * 8 + 2 * t, c1 = c0 + 1;
                float bb0 = sB1[c0], bb1 = sB1[c1];
                float w0 = sA2[c0], w1 = sA2[c1];
                s0 += fmaxf(acc[nf][0] + bb0, 0.f) * w0 + fmaxf(acc[nf][1] + bb1, 0.f) * w1;
                s1 += fmaxf(acc[nf][2] + bb0, 0.f) * w0 + fmaxf(acc[nf][3] + bb1, 0.f) * w1;
            }
            s0 += __shfl_xor_sync(0xffffffffu, s0, 1);
            s0 += __shfl_xor_sync(0xffffffffu, s0, 2);
            s1 += __shfl_xor_sync(0xffffffffu, s1, 1);
            s1 += __shfl_xor_sync(0xffffffffu, s1, 2);
            if (t == 0) {
                sAtt[rbase + g]     = 1.f / (1.f + expf(-(s0 + b2v)));
                sAtt[rbase + g + 8] = 1.f / (1.f + expf(-(s1 + b2v)));
            }
        }
        __syncwarp();

        for (int idx = lane; idx < 16 * 33; idx += 32) {
            int r = idx / 33, c = idx - r * 33;
            int rl = rbase + r;
            int grow = gbase + rl;
            if (grow < NPTS) {
                float a = sAtt[rl];
                int l = sLab[rl];
                float4 v = *(const float4*)(sA + rl * SA + c * 4);
                red4(g_agg + (size_t)l * 132 + c * 4,
                     v.x * a, v.y * a, v.z * a, v.w * a);
            }
        }
        __syncwarp();
    }
}

// ============ kernel 2: h = relu(agg @ oW1 + ob1)  (tf32 MMA) ============
// grid (148, 2): y = 64-col slice; persistent, per-warp pipelines
__global__ void __launch_bounds__(256, 2) gemmB_kernel(
    const float* __restrict__ oW1, const float* __restrict__ ob1)
{
    extern __shared__ char dynRaw[];
    float*    sA  = (float*)dynRaw;                       // 128*SA
    unsigned* sWb = (unsigned*)(dynRaw + 128 * SA * 4);   // 136*SB

    const int tid = threadIdx.x;
    const int slice = blockIdx.y;
    const float4* a4 = (const float4*)g_agg;   // 33 f4/row

    for (int idx = tid; idx < 136 * 64; idx += 256) {
        int k = idx >> 6, n = idx & 63;
        float v = (k < 131) ? oW1[k * 128 + slice * 64 + n] : 0.f;
        sWb[k * SB + n] = cvt_tf32(v);
    }
    __syncthreads();

    const int w = tid >> 5;
    const int lane = tid & 31;
    const int g = lane >> 2;
    const int t = lane & 3;
    const int rbase = w * 16;

    float bias0[8], bias1[8];
#pragma unroll
    for (int nf = 0; nf < 8; nf++) {
        int c0 = slice * 64 + nf * 8 + 2 * t;
        bias0[nf] = __ldg(ob1 + c0);
        bias1[nf] = __ldg(ob1 + c0 + 1);
    }

    for (int tile = blockIdx.x; tile < NTILE_M; tile += gridDim.x) {
        const int gbase = tile * 128;

        for (int idx = lane; idx < 16 * 33; idx += 32) {
            int r = idx / 33, c4 = idx - r * 33;
            int gr = gbase + rbase + r; if (gr >= MCLUS) gr = MCLUS - 1;
            cpasync16(sA + (rbase + r) * SA + c4 * 4, a4 + (size_t)gr * 33 + c4);
        }
        cp_commit();
        if (lane < 16) {   // zero A cols 132..135
            float* Ar = sA + (rbase + lane) * SA;
            Ar[132] = 0.f; Ar[133] = 0.f; Ar[134] = 0.f; Ar[135] = 0.f;
        }
        cp_wait0();
        __syncwarp();

        float acc[8][4];
#pragma unroll
        for (int nf = 0; nf < 8; nf++) {
            acc[nf][0] = 0.f; acc[nf][1] = 0.f; acc[nf][2] = 0.f; acc[nf][3] = 0.f;
        }

        const float* Ar0 = sA + (rbase + g) * SA;
        const float* Ar1 = Ar0 + 8 * SA;

#pragma unroll
        for (int kf = 0; kf < 17; kf++) {
            int k0 = kf * 8;
            unsigned a0 = cvt_tf32(Ar0[k0 + t]);
            unsigned a1 = cvt_tf32(Ar1[k0 + t]);
            unsigned a2 = cvt_tf32(Ar0[k0 + t + 4]);
            unsigned a3 = cvt_tf32(Ar1[k0 + t + 4]);
            const unsigned* B0 = sWb + (k0 + t) * SB + g;
            const unsigned* B1 = sWb + (k0 + t + 4) * SB + g;
#pragma unroll
            for (int nf = 0; nf < 8; nf++) {
                mma_tf32(acc[nf], a0, a1, a2, a3, B0[nf * 8], B1[nf * 8]);
            }
        }

        int r0 = gbase + rbase + g;
        int r1 = r0 + 8;
#pragma unroll
        for (int nf = 0; nf < 8; nf++) {
            int c0 = slice * 64 + nf * 8 + 2 * t;
            if (r0 < MCLUS)
                *(float2*)(g_h + (size_t)r0 * 128 + c0) =
                    make_float2(fmaxf(acc[nf][0] + bias0[nf], 0.f),
                                fmaxf(acc[nf][1] + bias1[nf], 0.f));
            if (r1 < MCLUS)
                *(float2*)(g_h + (size_t)r1 * 128 + c0) =
                    make_float2(fmaxf(acc[nf][2] + bias0[nf], 0.f),
                                fmaxf(acc[nf][3] + bias1[nf], 0.f));
        }
        __syncwarp();
    }
}

// ============ kernel 3: out = relu(h @ oW2 + ob2)  (tf32 MMA) ============
// grid (74, 4): y = 64-col slice; persistent, per-warp pipelines
__global__ void __launch_bounds__(256, 2) gemmC_kernel(
    const float* __restrict__ oW2, const float* __restrict__ ob2,
    float* __restrict__ out)
{
    extern __shared__ char dynRaw[];
    float*    sA  = (float*)dynRaw;                       // 128*SA
    unsigned* sWb = (unsigned*)(dynRaw + 128 * SA * 4);   // 128*SB

    const int tid = threadIdx.x;
    const int slice = blockIdx.y;
    const float4* h4 = (const float4*)g_h;   // 32 f4/row

    for (int idx = tid; idx < 128 * 64; idx += 256) {
        int k = idx >> 6, n = idx & 63;
        sWb[k * SB + n] = cvt_tf32(oW2[k * 256 + slice * 64 + n]);
    }
    __syncthreads();

    const int w = tid >> 5;
    const int lane = tid & 31;
    const int g = lane >> 2;
    const int t = lane & 3;
    const int rbase = w * 16;

    float bias0[8], bias1[8];
#pragma unroll
    for (int nf = 0; nf < 8; nf++) {
        int c0 = slice * 64 + nf * 8 + 2 * t;
        bias0[nf] = __ldg(ob2 + c0);
        bias1[nf] = __ldg(ob2 + c0 + 1);
    }

    for (int tile = blockIdx.x; tile < NTILE_M; tile += gridDim.x) {
        const int gbase = tile * 128;

        for (int idx = lane; idx < 16 * 32; idx += 32) {
            int r = idx >> 5, c4 = idx & 31;
            int gr = gbase + rbase + r; if (gr >= MCLUS) gr = MCLUS - 1;
            cpasync16(sA + (rbase + r) * SA + c4 * 4, h4 + (size_t)gr * 32 + c4);
        }
        cp_commit();
        cp_wait0();
        __syncwarp();

        float acc[8][4];
#pragma unroll
        for (int nf = 0; nf < 8; nf++) {
            acc[nf][0] = 0.f; acc[nf][1] = 0.f; acc[nf][2] = 0.f; acc[nf][3] = 0.f;
        }

        const float* Ar0 = sA + (rbase + g) * SA;
        const float* Ar1 = Ar0 + 8 * SA;

#pragma unroll
        for (int kf = 0; kf < 16; kf++) {
            int k0 = kf * 8;
            unsigned a0 = cvt_tf32(Ar0[k0 + t]);
            unsigned a1 = cvt_tf32(Ar1[k0 + t]);
            unsigned a2 = cvt_tf32(Ar0[k0 + t + 4]);
            unsigned a3 = cvt_tf32(Ar1[k0 + t + 4]);
            const unsigned* B0 = sWb + (k0 + t) * SB + g;
            const unsigned* B1 = sWb + (k0 + t + 4) * SB + g;
#pragma unroll
            for (int nf = 0; nf < 8; nf++) {
                mma_tf32(acc[nf], a0, a1, a2, a3, B0[nf * 8], B1[nf * 8]);
            }
        }

        int r0 = gbase + rbase + g;
        int r1 = r0 + 8;
#pragma unroll
        for (int nf = 0; nf < 8; nf++) {
            int c0 = slice * 64 + nf * 8 + 2 * t;
            if (r0 < MCLUS)
                *(float2*)(out + (size_t)r0 * 256 + c0) =
                    make_float2(fmaxf(acc[nf][0] + bias0[nf], 0.f),
                                fmaxf(acc[nf][1] + bias1[nf], 0.f));
            if (r1 < MCLUS)
                *(float2*)(out + (size_t)r1 * 256 + c0) =
                    make_float2(fmaxf(acc[nf][2] + bias0[nf], 0.f),
                                fmaxf(acc[nf][3] + bias1[nf], 0.f));
        }
        __syncwarp();
    }
}

extern "C" void kernel_launch(void* const* d_in, const int* in_sizes, int n_in,
                              void* d_out, int out_size) {
    const float* feat = (const float*)d_in[0];
    const float* pts  = (const float*)d_in[1];
    const float* ctr  = (const float*)d_in[2];
    const int*   lab  = (const int*)d_in[3];
    const float* aW1  = (const float*)d_in[4];
    const float* ab1  = (const float*)d_in[5];
    const float* aW2  = (const float*)d_in[6];
    const float* ab2  = (const float*)d_in[7];
    const float* oW1  = (const float*)d_in[8];
    const float* ob1  = (const float*)d_in[9];
    const float* oW2  = (const float*)d_in[10];
    const float* ob2  = (const float*)d_in[11];
    float* out = (float*)d_out;

    const int attSmem = 128 * SA * 4 + 136 * SB * 4 + (64 + 64 + 128) * 4 + 128 * 4 + 16;
    const int bSmem   = 128 * SA * 4 + 136 * SB * 4;
    const int cSmem   = 128 * SA * 4 + 128 * SB * 4;

    static int inited = 0;
    if (!inited) {
        cudaFuncSetAttribute(att_scatter_kernel, cudaFuncAttributeMaxDynamicSharedMemorySize, attSmem);
        cudaFuncSetAttribute(gemmB_kernel, cudaFuncAttributeMaxDynamicSharedMemorySize, bSmem);
        cudaFuncSetAttribute(gemmC_kernel, cudaFuncAttributeMaxDynamicSharedMemorySize, cSmem);
        inited = 1;
    }

    zero_agg_kernel<<<2048, 256>>>();
    att_scatter_kernel<<<296, 256, attSmem>>>(feat, pts, ctr, lab,
                                              aW1, ab1, aW2, ab2);
    gemmB_kernel<<<dim3(148, 2), 256, bSmem>>>(oW1, ob1);
    gemmC_kernel<<<dim3(74, 4), 256, cSmem>>>(oW2, ob2, out);
}

// round 16
// speedup vs baseline: 1.0912x; 1.0083x over previous
#include <cuda_runtime.h>
#include <math.h>

#define NPTS   500000
#define MCLUS  50000
#define NTILE_ATT ((NPTS + 127) / 128)    // 3907
#define NTILE_M   ((MCLUS + 127) / 128)   // 391

__device__ float g_agg[(size_t)MCLUS * 132];   // 131 used + 1 pad
__device__ float g_h[(size_t)MCLUS * 128];

// ---------------- helpers ----------------
__device__ __forceinline__ void red4(float* addr, float a, float b, float c, float d) {
    asm volatile("red.global.add.v4.f32 [%0], {%1,%2,%3,%4};"
                 :: "l"(addr), "f"(a), "f"(b), "f"(c), "f"(d) : "memory");
}
__device__ __forceinline__ void cpasync16(void* smem_dst, const void* gsrc) {
    unsigned saddr = (unsigned)__cvta_generic_to_shared(smem_dst);
    asm volatile("cp.async.cg.shared.global [%0], [%1], 16;" :: "r"(saddr), "l"(gsrc));
}
__device__ __forceinline__ void cp_commit() { asm volatile("cp.async.commit_group;"); }
__device__ __forceinline__ void cp_wait0() { asm volatile("cp.async.wait_group 0;" ::: "memory"); }
__device__ __forceinline__ void cp_wait1() { asm volatile("cp.async.wait_group 1;" ::: "memory"); }
__device__ __forceinline__ void cp_wait2() { asm volatile("cp.async.wait_group 2;" ::: "memory"); }
__device__ __forceinline__ void cp_wait3() { asm volatile("cp.async.wait_group 3;" ::: "memory"); }

__device__ __forceinline__ unsigned cvt_tf32(float f) {
    unsigned x;
    asm("cvt.rna.tf32.f32 %0, %1;" : "=r"(x) : "f"(f));
    return x;
}
__device__ __forceinline__ void mma_tf32(float* c, unsigned a0, unsigned a1,
                                         unsigned a2, unsigned a3,
                                         unsigned b0, unsigned b1) {
    asm volatile(
        "mma.sync.aligned.m16n8k8.row.col.f32.tf32.tf32.f32 "
        "{%0,%1,%2,%3}, {%4,%5,%6,%7}, {%8,%9}, {%0,%1,%2,%3};"
        : "+f"(c[0]), "+f"(c[1]), "+f"(c[2]), "+f"(c[3])
        : "r"(a0), "r"(a1), "r"(a2), "r"(a3), "r"(b0), "r"(b1));
}

#define SA 136   // A-tile row stride (floats): conflict-free
#define SB 72    // B-tile row stride (tf32 words): conflict-free

// one kf step of the m16n64 MMA
#define MMA_KF_STEP                                                            \
    {                                                                          \
        int k0 = kf * 8;                                                       \
        unsigned a0 = cvt_tf32(Ar0[k0 + t]);                                   \
        unsigned a1 = cvt_tf32(Ar1[k0 + t]);                                   \
        unsigned a2 = cvt_tf32(Ar0[k0 + t + 4]);                               \
        unsigned a3 = cvt_tf32(Ar1[k0 + t + 4]);                               \
        const unsigned* B0 = sWb + (k0 + t) * SB + g;                          \
        const unsigned* B1 = sWb + (k0 + t + 4) * SB + g;                      \
        _Pragma("unroll")                                                      \
        for (int nf = 0; nf < 8; nf++)                                         \
            mma_tf32(acc[nf], a0, a1, a2, a3, B0[nf * 8], B1[nf * 8]);         \
    }

// ---------------- kernel 0: zero agg ----------------
__global__ void zero_agg_kernel() {
    const size_t total4 = (size_t)MCLUS * 132 / 4;
    float4* p = (float4*)g_agg;
    float4 z = make_float4(0.f, 0.f, 0.f, 0.f);
    for (size_t i = blockIdx.x * blockDim.x + threadIdx.x; i < total4;
         i += (size_t)gridDim.x * blockDim.x)
        p[i] = z;
}

// ============ kernel 1: attention MLP (tf32 MMA) + scatter ============
// Persistent per-warp pipelines; K-progressive staging (4 cp.async groups).
__global__ void __launch_bounds__(256, 2) att_scatter_kernel(
    const float* __restrict__ feat, const float* __restrict__ pts,
    const float* __restrict__ ctr, const int* __restrict__ lab,
    const float* __restrict__ aW1, const float* __restrict__ ab1,
    const float* __restrict__ aW2, const float* __restrict__ ab2)
{
    extern __shared__ char dynRaw[];
    float*    sA  = (float*)dynRaw;                       // 128*SA floats
    unsigned* sWb = (unsigned*)(dynRaw + 128 * SA * 4);   // 136*SB tf32 bits
    float*    sB1 = (float*)(dynRaw + 128 * SA * 4 + 136 * SB * 4);  // 64
    float*    sA2 = sB1 + 64;          // 64
    float*    sAtt = sA2 + 64;         // 128
    int*      sLab = (int*)(sAtt + 128);  // 128
    float*    sb2p = (float*)(sLab + 128);

    const int tid = threadIdx.x;
    const float4* f4 = (const float4*)feat;

    for (int idx = tid; idx < 136 * 64; idx += 256) {
        int k = idx >> 6, n = idx & 63;
        float v = (k < 131) ? aW1[k * 64 + n] : 0.f;
        sWb[k * SB + n] = cvt_tf32(v);
    }
    if (tid < 64) { sB1[tid] = ab1[tid]; sA2[tid] = aW2[tid]; }
    if (tid == 0) *sb2p = ab2[0];
    __syncthreads();

    const int w = tid >> 5;
    const int lane = tid & 31;
    const int g = lane >> 2;
    const int t = lane & 3;
    const int rbase = w * 16;
    const int rg4 = (lane >> 3) * 4;   // staging row group
    const int cb  = lane & 7;          // staging column base
    const float b2v = *sb2p;

    for (int tile = blockIdx.x; tile < NTILE_ATT; tile += gridDim.x) {
        const int gbase = tile * 128;

        // K-progressive staging: group j = columns [8j, 8j+8) for all 16 rows
#pragma unroll
        for (int j = 0; j < 4; j++) {
            int c4 = cb + 8 * j;
#pragma unroll
            for (int i = 0; i < 4; i++) {
                int rl = rbase + rg4 + i;
                int gr = gbase + rl; if (gr >= NPTS) gr = NPTS - 1;
                cpasync16(sA + rl * SA + c4 * 4, f4 + (size_t)gr * 32 + c4);
            }
            cp_commit();
        }
        if (lane < 16) {
            int rl = rbase + lane;
            int row = gbase + rl;
            int rc = (row < NPTS) ? row : (NPTS - 1);
            int l = lab[rc];
            sLab[rl] = l;
            float* Ar = sA + rl * SA;
            Ar[128] = ctr[l * 3 + 0] - pts[rc * 3 + 0];
            Ar[129] = ctr[l * 3 + 1] - pts[rc * 3 + 1];
            Ar[130] = ctr[l * 3 + 2] - pts[rc * 3 + 2];
            Ar[131] = 0.f; Ar[132] = 0.f; Ar[133] = 0.f; Ar[134] = 0.f; Ar[135] = 0.f;
        }

        float acc[8][4];
#pragma unroll
        for (int nf = 0; nf < 8; nf++) {
            acc[nf][0] = 0.f; acc[nf][1] = 0.f; acc[nf][2] = 0.f; acc[nf][3] = 0.f;
        }

        const float* Ar0 = sA + (rbase + g) * SA;
        const float* Ar1 = Ar0 + 8 * SA;

        cp_wait3(); __syncwarp();
#pragma unroll
        for (int kf = 0; kf < 4; kf++) MMA_KF_STEP
        cp_wait2(); __syncwarp();
#pragma unroll
        for (int kf = 4; kf < 8; kf++) MMA_KF_STEP
        cp_wait1(); __syncwarp();
#pragma unroll
        for (int kf = 8; kf < 12; kf++) MMA_KF_STEP
        cp_wait0(); __syncwarp();
#pragma unroll
        for (int kf = 12; kf < 17; kf++) MMA_KF_STEP

        {
            float s0 = 0.f, s1 = 0.f;
#pragma unroll
            for (int nf = 0; nf < 8; nf++) {
                int c0 = nf * 8 + 2 * t, c1 = c0 + 1;
                float bb0 = sB1[c0], bb1 = sB1[c1];
                float w0 = sA2[c0], w1 = sA2[c1];
                s0 += fmaxf(acc[nf][0] + bb0, 0.f) * w0 + fmaxf(acc[nf][1] + bb1, 0.f) * w1;
                s1 += fmaxf(acc[nf][2] + bb0, 0.f) * w0 + fmaxf(acc[nf][3] + bb1, 0.f) * w1;
            }
            s0 += __shfl_xor_sync(0xffffffffu, s0, 1);
            s0 += __shfl_xor_sync(0xffffffffu, s0, 2);
            s1 += __shfl_xor_sync(0xffffffffu, s1, 1);
            s1 += __shfl_xor_sync(0xffffffffu, s1, 2);
            if (t == 0) {
                sAtt[rbase + g]     = 1.f / (1.f + expf(-(s0 + b2v)));
                sAtt[rbase + g + 8] = 1.f / (1.f + expf(-(s1 + b2v)));
            }
        }
        __syncwarp();

        for (int idx = lane; idx < 16 * 33; idx += 32) {
            int r = idx / 33, c = idx - r * 33;
            int rl = rbase + r;
            int grow = gbase + rl;
            if (grow < NPTS) {
                float a = sAtt[rl];
                int l = sLab[rl];
                float4 v = *(const float4*)(sA + rl * SA + c * 4);
                red4(g_agg + (size_t)l * 132 + c * 4,
                     v.x * a, v.y * a, v.z * a, v.w * a);
            }
        }
        __syncwarp();
    }
}

// ============ kernel 2: h = relu(agg @ oW1 + ob1)  (tf32 MMA) ============
// grid (148, 2); persistent per-warp pipelines; K-progressive staging
__global__ void __launch_bounds__(256, 2) gemmB_kernel(
    const float* __restrict__ oW1, const float* __restrict__ ob1)
{
    extern __shared__ char dynRaw[];
    float*    sA  = (float*)dynRaw;                       // 128*SA
    unsigned* sWb = (unsigned*)(dynRaw + 128 * SA * 4);   // 136*SB

    const int tid = threadIdx.x;
    const int slice = blockIdx.y;
    const float4* a4 = (const float4*)g_agg;   // 33 f4/row

    for (int idx = tid; idx < 136 * 64; idx += 256) {
        int k = idx >> 6, n = idx & 63;
        float v = (k < 131) ? oW1[k * 128 + slice * 64 + n] : 0.f;
        sWb[k * SB + n] = cvt_tf32(v);
    }
    __syncthreads();

    const int w = tid >> 5;
    const int lane = tid & 31;
    const int g = lane >> 2;
    const int t = lane & 3;
    const int rbase = w * 16;
    const int rg4 = (lane >> 3) * 4;
    const int cb  = lane & 7;

    float bias0[8], bias1[8];
#pragma unroll
    for (int nf = 0; nf < 8; nf++) {
        int c0 = slice * 64 + nf * 8 + 2 * t;
        bias0[nf] = __ldg(ob1 + c0);
        bias1[nf] = __ldg(ob1 + c0 + 1);
    }

    for (int tile = blockIdx.x; tile < NTILE_M; tile += gridDim.x) {
        const int gbase = tile * 128;

#pragma unroll
        for (int j = 0; j < 4; j++) {
            int c4 = cb + 8 * j;
#pragma unroll
            for (int i = 0; i < 4; i++) {
                int rl = rbase + rg4 + i;
                int gr = gbase + rl; if (gr >= MCLUS) gr = MCLUS - 1;
                cpasync16(sA + rl * SA + c4 * 4, a4 + (size_t)gr * 33 + c4);
                if (j == 3 && cb == 0)   // c4 = 32 tail chunk
                    cpasync16(sA + rl * SA + 32 * 4, a4 + (size_t)gr * 33 + 32);
            }
            cp_commit();
        }
        if (lane < 16) {   // zero A cols 132..135
            float* Ar = sA + (rbase + lane) * SA;
            Ar[132] = 0.f; Ar[133] = 0.f; Ar[134] = 0.f; Ar[135] = 0.f;
        }

        float acc[8][4];
#pragma unroll
        for (int nf = 0; nf < 8; nf++) {
            acc[nf][0] = 0.f; acc[nf][1] = 0.f; acc[nf][2] = 0.f; acc[nf][3] = 0.f;
        }

        const float* Ar0 = sA + (rbase + g) * SA;
        const float* Ar1 = Ar0 + 8 * SA;

        cp_wait3(); __syncwarp();
#pragma unroll
        for (int kf = 0; kf < 4; kf++) MMA_KF_STEP
        cp_wait2(); __syncwarp();
#pragma unroll
        for (int kf = 4; kf < 8; kf++) MMA_KF_STEP
        cp_wait1(); __syncwarp();
#pragma unroll
        for (int kf = 8; kf < 12; kf++) MMA_KF_STEP
        cp_wait0(); __syncwarp();
#pragma unroll
        for (int kf = 12; kf < 17; kf++) MMA_KF_STEP

        int r0 = gbase + rbase + g;
        int r1 = r0 + 8;
#pragma unroll
        for (int nf = 0; nf < 8; nf++) {
            int c0 = slice * 64 + nf * 8 + 2 * t;
            if (r0 < MCLUS)
                *(float2*)(g_h + (size_t)r0 * 128 + c0) =
                    make_float2(fmaxf(acc[nf][0] + bias0[nf], 0.f),
                                fmaxf(acc[nf][1] + bias1[nf], 0.f));
            if (r1 < MCLUS)
                *(float2*)(g_h + (size_t)r1 * 128 + c0) =
                    make_float2(fmaxf(acc[nf][2] + bias0[nf], 0.f),
                                fmaxf(acc[nf][3] + bias1[nf], 0.f));
        }
        __syncwarp();
    }
}

// ============ kernel 3: out = relu(h @ oW2 + ob2)  (tf32 MMA) ============
// grid (74, 4); persistent per-warp pipelines; K-progressive staging
__global__ void __launch_bounds__(256, 2) gemmC_kernel(
    const float* __restrict__ oW2, const float* __restrict__ ob2,
    float* __restrict__ out)
{
    extern __shared__ char dynRaw[];
    float*    sA  = (float*)dynRaw;                       // 128*SA
    unsigned* sWb = (unsigned*)(dynRaw + 128 * SA * 4);   // 128*SB

    const int tid = threadIdx.x;
    const int slice = blockIdx.y;
    const float4* h4 = (const float4*)g_h;   // 32 f4/row

    for (int idx = tid; idx < 128 * 64; idx += 256) {
        int k = idx >> 6, n = idx & 63;
        sWb[k * SB + n] = cvt_tf32(oW2[k * 256 + slice * 64 + n]);
    }
    __syncthreads();

    const int w = tid >> 5;
    const int lane = tid & 31;
    const int g = lane >> 2;
    const int t = lane & 3;
    const int rbase = w * 16;
    const int rg4 = (lane >> 3) * 4;
    const int cb  = lane & 7;

    float bias0[8], bias1[8];
#pragma unroll
    for (int nf = 0; nf < 8; nf++) {
        int c0 = slice * 64 + nf * 8 + 2 * t;
        bias0[nf] = __ldg(ob2 + c0);
        bias1[nf] = __ldg(ob2 + c0 + 1);
    }

    for (int tile = blockIdx.x; tile < NTILE_M; tile += gridDim.x) {
        const int gbase = tile * 128;

#pragma unroll
        for (int j = 0; j < 4; j++) {
            int c4 = cb + 8 * j;
#pragma unroll
            for (int i = 0; i < 4; i++) {
                int rl = rbase + rg4 + i;
                int gr = gbase + rl; if (gr >= MCLUS) gr = MCLUS - 1;
                cpasync16(sA + rl * SA + c4 * 4, h4 + (size_t)gr * 32 + c4);
            }
            cp_commit();
        }

        float acc[8][4];
#pragma unroll
        for (int nf = 0; nf < 8; nf++) {
            acc[nf][0] = 0.f; acc[nf][1] = 0.f; acc[nf][2] = 0.f; acc[nf][3] = 0.f;
        }

        const float* Ar0 = sA + (rbase + g) * SA;
        const float* Ar1 = Ar0 + 8 * SA;

        cp_wait3(); __syncwarp();
#pragma unroll
        for (int kf = 0; kf < 4; kf++) MMA_KF_STEP
        cp_wait2(); __syncwarp();
#pragma unroll
        for (int kf = 4; kf < 8; kf++) MMA_KF_STEP
        cp_wait1(); __syncwarp();
#pragma unroll
        for (int kf = 8; kf < 12; kf++) MMA_KF_STEP
        cp_wait0(); __syncwarp();
#pragma unroll
        for (int kf = 12; kf < 16; kf++) MMA_KF_STEP

        int r0 = gbase + rbase + g;
        int r1 = r0 + 8;
#pragma unroll
        for (int nf = 0; nf < 8; nf++) {
            int c0 = slice * 64 + nf * 8 + 2 * t;
            if (r0 < MCLUS)
                *(float2*)(out + (size_t)r0 * 256 + c0) =
                    make_float2(fmaxf(acc[nf][0] + bias0[nf], 0.f),
                                fmaxf(acc[nf][1] + bias1[nf], 0.f));
            if (r1 < MCLUS)
                *(float2*)(out + (size_t)r1 * 256 + c0) =
                    make_float2(fmaxf(acc[nf][2] + bias0[nf], 0.f),
                                fmaxf(acc[nf][3] + bias1[nf], 0.f));
        }
        __syncwarp();
    }
}

extern "C" void kernel_launch(void* const* d_in, const int* in_sizes, int n_in,
                              void* d_out, int out_size) {
    const float* feat = (const float*)d_in[0];
    const float* pts  = (const float*)d_in[1];
    const float* ctr  = (const float*)d_in[2];
    const int*   lab  = (const int*)d_in[3];
    const float* aW1  = (const float*)d_in[4];
    const float* ab1  = (const float*)d_in[5];
    const float* aW2  = (const float*)d_in[6];
    const float* ab2  = (const float*)d_in[7];
    const float* oW1  = (const float*)d_in[8];
    const float* ob1  = (const float*)d_in[9];
    const float* oW2  = (const float*)d_in[10];
    const float* ob2  = (const float*)d_in[11];
    float* out = (float*)d_out;

    const int attSmem = 128 * SA * 4 + 136 * SB * 4 + (64 + 64 + 128) * 4 + 128 * 4 + 16;
    const int bSmem   = 128 * SA * 4 + 136 * SB * 4;
    const int cSmem   = 128 * SA * 4 + 128 * SB * 4;

    static int inited = 0;
    if (!inited) {
        cudaFuncSetAttribute(att_scatter_kernel, cudaFuncAttributeMaxDynamicSharedMemorySize, attSmem);
        cudaFuncSetAttribute(gemmB_kernel, cudaFuncAttributeMaxDynamicSharedMemorySize, bSmem);
        cudaFuncSetAttribute(gemmC_kernel, cudaFuncAttributeMaxDynamicSharedMemorySize, cSmem);
        inited = 1;
    }

    zero_agg_kernel<<<2048, 256>>>();
    att_scatter_kernel<<<296, 256, attSmem>>>(feat, pts, ctr, lab,
                                              aW1, ab1, aW2, ab2);
    gemmB_kernel<<<dim3(148, 2), 256, bSmem>>>(oW1, ob1);
    gemmC_kernel<<<dim3(74, 4), 256, cSmem>>>(oW2, ob2, out);
}